// round 1
// baseline (speedup 1.0000x reference)
#include <cuda_runtime.h>
#include <math.h>

// Problem constants
#define BB 64
#define TT 2048
#define HH 512   // ENC_H == DEC_H
#define PP 256
#define SPLITS 16
#define ROWS_PER_SPLIT (TT / SPLITS)   // 128
#define ROWS_PER_WARP  (ROWS_PER_SPLIT / 8)  // 16

// Scratch (no allocations allowed -> __device__ globals)
__device__ float g_scores[BB * TT];          // raw logits
__device__ float g_u[BB * HH];               // Wk @ q[b]
__device__ float g_c[BB];                    // bk . q[b]
__device__ float g_pm[BB * SPLITS];          // per-split max
__device__ float g_pz[BB * SPLITS];          // per-split sum-exp
__device__ float g_pw[BB * SPLITS * HH];     // per-split weighted row-sum

// ---------------------------------------------------------------------------
// Kernel A: q[b] = dec[b]@Wq + bq ; u[b] = Wk @ q[b] ; c[b] = bk . q[b]
// 64 blocks x 256 threads. Weights live in L2 after first wave.
// ---------------------------------------------------------------------------
__global__ void prep_kernel(const float* __restrict__ dec,
                            const float* __restrict__ Wk,
                            const float* __restrict__ bk,
                            const float* __restrict__ Wq,
                            const float* __restrict__ bq) {
    __shared__ float sdec[HH];
    __shared__ float sq[PP];
    __shared__ float red[256];
    int b = blockIdx.x, tid = threadIdx.x;

    for (int i = tid; i < HH; i += 256) sdec[i] = dec[b * HH + i];
    __syncthreads();

    // query[p], p = tid (Wq column reads are coalesced across threads)
    float acc = bq[tid];
#pragma unroll 4
    for (int e = 0; e < HH; e++) acc = fmaf(sdec[e], Wq[e * PP + tid], acc);
    sq[tid] = acc;
    __syncthreads();

    // u[e] for e = tid, tid+256
    for (int e = tid; e < HH; e += 256) {
        float a = 0.f;
        const float* wrow = Wk + (size_t)e * PP;
#pragma unroll 4
        for (int p = 0; p < PP; p++) a = fmaf(wrow[p], sq[p], a);
        g_u[b * HH + e] = a;
    }

    // c = sum_p bk[p]*q[p]
    red[tid] = bk[tid] * sq[tid];
    __syncthreads();
    for (int s = 128; s > 0; s >>= 1) {
        if (tid < s) red[tid] += red[tid + s];
        __syncthreads();
    }
    if (tid == 0) g_c[b] = red[0];
}

// ---------------------------------------------------------------------------
// Kernel B: streaming pass over encoder_outputs.
// grid = (SPLITS, B), block = 256 (8 warps). Each warp handles 16 contiguous
// rows: s = enc_row . u + c (warp-shfl reduce), online softmax accumulating
// Z and w = sum exp * enc_row (per-lane float4 ownership: element
// (j*32+lane)*4+k). Warp partials combined to one per-block (split) partial.
// ---------------------------------------------------------------------------
__global__ void __launch_bounds__(256, 4)
score_kernel(const float* __restrict__ enc) {
    int b = blockIdx.y, sp = blockIdx.x;
    int warp = threadIdx.x >> 5, lane = threadIdx.x & 31;

    const float4* u4 = (const float4*)(g_u + b * HH);
    float4 U0 = u4[0 * 32 + lane];
    float4 U1 = u4[1 * 32 + lane];
    float4 U2 = u4[2 * 32 + lane];
    float4 U3 = u4[3 * 32 + lane];
    float c = g_c[b];

    const float4* e4 = (const float4*)(enc + (size_t)b * TT * HH);
    int t0 = sp * ROWS_PER_SPLIT + warp * ROWS_PER_WARP;

    float m = -INFINITY, Z = 0.f;
    float4 W0 = make_float4(0, 0, 0, 0);
    float4 W1 = make_float4(0, 0, 0, 0);
    float4 W2 = make_float4(0, 0, 0, 0);
    float4 W3 = make_float4(0, 0, 0, 0);

#pragma unroll 2
    for (int r = 0; r < ROWS_PER_WARP; r++) {
        int t = t0 + r;
        const float4* row = e4 + (size_t)t * (HH / 4);
        float4 x0 = row[0 * 32 + lane];
        float4 x1 = row[1 * 32 + lane];
        float4 x2 = row[2 * 32 + lane];
        float4 x3 = row[3 * 32 + lane];

        float s = x0.x * U0.x + x0.y * U0.y + x0.z * U0.z + x0.w * U0.w
                + x1.x * U1.x + x1.y * U1.y + x1.z * U1.z + x1.w * U1.w
                + x2.x * U2.x + x2.y * U2.y + x2.z * U2.z + x2.w * U2.w
                + x3.x * U3.x + x3.y * U3.y + x3.z * U3.z + x3.w * U3.w;
#pragma unroll
        for (int o = 16; o > 0; o >>= 1) s += __shfl_xor_sync(0xFFFFFFFFu, s, o);
        s += c;
        if (lane == 0) g_scores[b * TT + t] = s;

        float nm = fmaxf(m, s);
        float rs = __expf(m - nm);   // 0 on first iter (m = -inf)
        float p  = __expf(s - nm);
        Z = Z * rs + p;
        W0.x = W0.x * rs + p * x0.x; W0.y = W0.y * rs + p * x0.y;
        W0.z = W0.z * rs + p * x0.z; W0.w = W0.w * rs + p * x0.w;
        W1.x = W1.x * rs + p * x1.x; W1.y = W1.y * rs + p * x1.y;
        W1.z = W1.z * rs + p * x1.z; W1.w = W1.w * rs + p * x1.w;
        W2.x = W2.x * rs + p * x2.x; W2.y = W2.y * rs + p * x2.y;
        W2.z = W2.z * rs + p * x2.z; W2.w = W2.w * rs + p * x2.w;
        W3.x = W3.x * rs + p * x3.x; W3.y = W3.y * rs + p * x3.y;
        W3.z = W3.z * rs + p * x3.z; W3.w = W3.w * rs + p * x3.w;
        m = nm;
    }

    // Block-combine 8 warp partials -> one split partial
    __shared__ float sm[8], sz[8];
    __shared__ float4 sw4[8][HH / 4];
    if (lane == 0) { sm[warp] = m; sz[warp] = Z; }
    sw4[warp][0 * 32 + lane] = W0;
    sw4[warp][1 * 32 + lane] = W1;
    sw4[warp][2 * 32 + lane] = W2;
    sw4[warp][3 * 32 + lane] = W3;
    __syncthreads();

    float M = -INFINITY;
#pragma unroll
    for (int w = 0; w < 8; w++) M = fmaxf(M, sm[w]);
    float f[8];
    float Zb = 0.f;
#pragma unroll
    for (int w = 0; w < 8; w++) { f[w] = __expf(sm[w] - M); Zb += sz[w] * f[w]; }

    int idx = b * SPLITS + sp;
    if (threadIdx.x == 0) { g_pm[idx] = M; g_pz[idx] = Zb; }

    const float* sw = (const float*)sw4;
    for (int e = threadIdx.x; e < HH; e += 256) {
        float a = 0.f;
#pragma unroll
        for (int w = 0; w < 8; w++) a = fmaf(sw[w * HH + e], f[w], a);
        g_pw[(size_t)idx * HH + e] = a;
    }
}

// ---------------------------------------------------------------------------
// Kernel C: per-batch final combine. 64 blocks x 256 threads.
// M,Z over splits; w/Z -> context = w@Wv + bv; attn = exp(s-M)/Z.
// ---------------------------------------------------------------------------
__global__ void finalize_kernel(const float* __restrict__ Wv,
                                const float* __restrict__ bv,
                                float* __restrict__ out_ctx,
                                float* __restrict__ out_attn) {
    int b = blockIdx.x, tid = threadIdx.x;
    __shared__ float wsh[HH];

    float M = -INFINITY;
#pragma unroll
    for (int j = 0; j < SPLITS; j++) M = fmaxf(M, g_pm[b * SPLITS + j]);
    float f[SPLITS];
    float Z = 0.f;
#pragma unroll
    for (int j = 0; j < SPLITS; j++) {
        f[j] = __expf(g_pm[b * SPLITS + j] - M);
        Z += g_pz[b * SPLITS + j] * f[j];
    }
    float invZ = 1.f / Z;

    for (int e = tid; e < HH; e += 256) {
        float a = 0.f;
#pragma unroll
        for (int j = 0; j < SPLITS; j++)
            a = fmaf(g_pw[(size_t)(b * SPLITS + j) * HH + e], f[j], a);
        wsh[e] = a * invZ;
    }
    __syncthreads();

    // context[b, tid] — Wv column reads coalesced across threads
    float acc = bv[tid];
#pragma unroll 4
    for (int e = 0; e < HH; e++) acc = fmaf(wsh[e], Wv[e * PP + tid], acc);
    out_ctx[b * PP + tid] = acc;

    // attn
    for (int t = tid; t < TT; t += 256)
        out_attn[b * TT + t] = __expf(g_scores[b * TT + t] - M) * invZ;
}

// ---------------------------------------------------------------------------
// Launch. Input order (metadata): dec, enc, encoder_lens(unused), Wk, bk,
// Wv, bv, Wq, bq. Output: [context (B*P) | attn (B*T)] float32.
// ---------------------------------------------------------------------------
extern "C" void kernel_launch(void* const* d_in, const int* in_sizes, int n_in,
                              void* d_out, int out_size) {
    const float* dec = (const float*)d_in[0];
    const float* enc = (const float*)d_in[1];
    const float* Wk  = (const float*)d_in[3];
    const float* bk  = (const float*)d_in[4];
    const float* Wv  = (const float*)d_in[5];
    const float* bv  = (const float*)d_in[6];
    const float* Wq  = (const float*)d_in[7];
    const float* bq  = (const float*)d_in[8];
    float* out = (float*)d_out;

    prep_kernel<<<BB, 256>>>(dec, Wk, bk, Wq, bq);
    score_kernel<<<dim3(SPLITS, BB), 256>>>(enc);
    finalize_kernel<<<BB, 256>>>(Wv, bv, out, out + BB * PP);
}

// round 2
// speedup vs baseline: 2.1613x; 2.1613x over previous
#include <cuda_runtime.h>
#include <math.h>

// Problem constants
#define BB 64
#define TT 2048
#define HH 512   // ENC_H == DEC_H
#define PP 256
#define SPLITS 16
#define ROWS_PER_SPLIT (TT / SPLITS)   // 128
#define ROWS_PER_WARP  (ROWS_PER_SPLIT / 8)  // 16

// Scratch (no allocations allowed -> __device__ globals)
__device__ float g_scores[BB * TT];          // raw logits
__device__ float g_u[BB * HH];               // Wk @ q[b]
__device__ float g_c[BB];                    // bk . q[b]
__device__ float g_pm[BB * SPLITS];          // per-split max
__device__ float g_pz[BB * SPLITS];          // per-split sum-exp
__device__ float g_pw[BB * SPLITS * HH];     // per-split weighted row-sum

// ---------------------------------------------------------------------------
// Kernel A: q[b] = dec[b]@Wq + bq ; u[b] = Wk @ q[b] ; c[b] = bk . q[b]
// 64 blocks x 256 threads.
//  - q: Wq staged through smem in 32-row tiles (coalesced float4 bulk loads),
//    fmas fed from smem (bank-conflict-free: stride 256 % 32 == 0).
//  - u: warp-per-row, lane-split reduction -> Wk reads fully coalesced;
//    two rows interleaved to overlap the shfl chains.
// ---------------------------------------------------------------------------
__global__ void __launch_bounds__(256)
prep_kernel(const float* __restrict__ dec,
            const float* __restrict__ Wk,
            const float* __restrict__ bk,
            const float* __restrict__ Wq,
            const float* __restrict__ bq) {
    __shared__ float sdec[HH];
    __shared__ float sW[32 * PP];   // 32KB tile
    __shared__ float sq[PP];
    __shared__ float red[256];
    int b = blockIdx.x, tid = threadIdx.x;

    for (int i = tid; i < HH; i += 256) sdec[i] = dec[b * HH + i];

    // --- q[p] for p = tid ---
    float acc = bq[tid];
    for (int t = 0; t < HH / 32; t++) {
        __syncthreads();
        const float4* src = (const float4*)(Wq + (size_t)t * 32 * PP);
        float4* dst = (float4*)sW;
#pragma unroll
        for (int i = 0; i < 8; i++) dst[tid + i * 256] = src[tid + i * 256];
        __syncthreads();
#pragma unroll
        for (int e = 0; e < 32; e++)
            acc = fmaf(sdec[t * 32 + e], sW[e * PP + tid], acc);
    }
    sq[tid] = acc;

    // --- c = bk . q ---
    red[tid] = bk[tid] * acc;
    __syncthreads();
    for (int s = 128; s > 0; s >>= 1) {
        if (tid < s) red[tid] += red[tid + s];
        __syncthreads();
    }
    if (tid == 0) g_c[b] = red[0];

    // --- u[e] = Wk[e,:] . q  (warp per row, coalesced, 2 rows interleaved) ---
    int warp = tid >> 5, lane = tid & 31;
    int p0 = lane * 8;
    float q0 = sq[p0 + 0], q1 = sq[p0 + 1], q2 = sq[p0 + 2], q3 = sq[p0 + 3];
    float q4 = sq[p0 + 4], q5 = sq[p0 + 5], q6 = sq[p0 + 6], q7 = sq[p0 + 7];
    for (int e = warp; e < HH; e += 16) {
        int e2 = e + 8;
        const float4* rA = (const float4*)(Wk + (size_t)e * PP);
        const float4* rB = (const float4*)(Wk + (size_t)e2 * PP);
        float4 a0 = rA[lane * 2], a1 = rA[lane * 2 + 1];
        float4 b0 = rB[lane * 2], b1 = rB[lane * 2 + 1];
        float sa = a0.x * q0 + a0.y * q1 + a0.z * q2 + a0.w * q3
                 + a1.x * q4 + a1.y * q5 + a1.z * q6 + a1.w * q7;
        float sb = b0.x * q0 + b0.y * q1 + b0.z * q2 + b0.w * q3
                 + b1.x * q4 + b1.y * q5 + b1.z * q6 + b1.w * q7;
#pragma unroll
        for (int o = 16; o > 0; o >>= 1) {
            sa += __shfl_xor_sync(0xFFFFFFFFu, sa, o);
            sb += __shfl_xor_sync(0xFFFFFFFFu, sb, o);
        }
        if (lane == 0) {
            g_u[b * HH + e]  = sa;
            g_u[b * HH + e2] = sb;
        }
    }
}

// ---------------------------------------------------------------------------
// Kernel B: streaming pass over encoder_outputs.
// grid = (SPLITS, B), block = 256 (8 warps). Each warp handles 16 contiguous
// rows, 2 rows per iteration (8 float4 = 128B/lane in flight). Interleaved
// shfl reductions, combined online-softmax update.
// ---------------------------------------------------------------------------
__global__ void __launch_bounds__(256)
score_kernel(const float* __restrict__ enc) {
    int b = blockIdx.y, sp = blockIdx.x;
    int warp = threadIdx.x >> 5, lane = threadIdx.x & 31;

    const float4* u4 = (const float4*)(g_u + b * HH);
    float4 U0 = u4[0 * 32 + lane];
    float4 U1 = u4[1 * 32 + lane];
    float4 U2 = u4[2 * 32 + lane];
    float4 U3 = u4[3 * 32 + lane];
    float c = g_c[b];

    const float4* e4 = (const float4*)(enc + (size_t)b * TT * HH);
    int t0 = sp * ROWS_PER_SPLIT + warp * ROWS_PER_WARP;

    float m = -INFINITY, Z = 0.f;
    float4 W0 = make_float4(0, 0, 0, 0);
    float4 W1 = make_float4(0, 0, 0, 0);
    float4 W2 = make_float4(0, 0, 0, 0);
    float4 W3 = make_float4(0, 0, 0, 0);

    for (int r = 0; r < ROWS_PER_WARP; r += 2) {
        int t = t0 + r;
        const float4* rowA = e4 + (size_t)t * (HH / 4);
        const float4* rowB = rowA + (HH / 4);
        float4 a0 = rowA[0 * 32 + lane];
        float4 a1 = rowA[1 * 32 + lane];
        float4 a2 = rowA[2 * 32 + lane];
        float4 a3 = rowA[3 * 32 + lane];
        float4 b0 = rowB[0 * 32 + lane];
        float4 b1 = rowB[1 * 32 + lane];
        float4 b2 = rowB[2 * 32 + lane];
        float4 b3 = rowB[3 * 32 + lane];

        float s1 = a0.x * U0.x + a0.y * U0.y + a0.z * U0.z + a0.w * U0.w
                 + a1.x * U1.x + a1.y * U1.y + a1.z * U1.z + a1.w * U1.w
                 + a2.x * U2.x + a2.y * U2.y + a2.z * U2.z + a2.w * U2.w
                 + a3.x * U3.x + a3.y * U3.y + a3.z * U3.z + a3.w * U3.w;
        float s2 = b0.x * U0.x + b0.y * U0.y + b0.z * U0.z + b0.w * U0.w
                 + b1.x * U1.x + b1.y * U1.y + b1.z * U1.z + b1.w * U1.w
                 + b2.x * U2.x + b2.y * U2.y + b2.z * U2.z + b2.w * U2.w
                 + b3.x * U3.x + b3.y * U3.y + b3.z * U3.z + b3.w * U3.w;
#pragma unroll
        for (int o = 16; o > 0; o >>= 1) {
            s1 += __shfl_xor_sync(0xFFFFFFFFu, s1, o);
            s2 += __shfl_xor_sync(0xFFFFFFFFu, s2, o);
        }
        s1 += c;
        s2 += c;
        if (lane == 0) {
            g_scores[b * TT + t]     = s1;
            g_scores[b * TT + t + 1] = s2;
        }

        float nm = fmaxf(m, fmaxf(s1, s2));
        float rs = __expf(m - nm);   // 0 on first iter (m = -inf)
        float p1 = __expf(s1 - nm);
        float p2 = __expf(s2 - nm);
        Z = Z * rs + p1 + p2;
        W0.x = W0.x * rs + p1 * a0.x + p2 * b0.x;
        W0.y = W0.y * rs + p1 * a0.y + p2 * b0.y;
        W0.z = W0.z * rs + p1 * a0.z + p2 * b0.z;
        W0.w = W0.w * rs + p1 * a0.w + p2 * b0.w;
        W1.x = W1.x * rs + p1 * a1.x + p2 * b1.x;
        W1.y = W1.y * rs + p1 * a1.y + p2 * b1.y;
        W1.z = W1.z * rs + p1 * a1.z + p2 * b1.z;
        W1.w = W1.w * rs + p1 * a1.w + p2 * b1.w;
        W2.x = W2.x * rs + p1 * a2.x + p2 * b2.x;
        W2.y = W2.y * rs + p1 * a2.y + p2 * b2.y;
        W2.z = W2.z * rs + p1 * a2.z + p2 * b2.z;
        W2.w = W2.w * rs + p1 * a2.w + p2 * b2.w;
        W3.x = W3.x * rs + p1 * a3.x + p2 * b3.x;
        W3.y = W3.y * rs + p1 * a3.y + p2 * b3.y;
        W3.z = W3.z * rs + p1 * a3.z + p2 * b3.z;
        W3.w = W3.w * rs + p1 * a3.w + p2 * b3.w;
        m = nm;
    }

    // Block-combine 8 warp partials -> one split partial
    __shared__ float sm[8], sz[8];
    __shared__ float4 sw4[8][HH / 4];
    if (lane == 0) { sm[warp] = m; sz[warp] = Z; }
    sw4[warp][0 * 32 + lane] = W0;
    sw4[warp][1 * 32 + lane] = W1;
    sw4[warp][2 * 32 + lane] = W2;
    sw4[warp][3 * 32 + lane] = W3;
    __syncthreads();

    float M = -INFINITY;
#pragma unroll
    for (int w = 0; w < 8; w++) M = fmaxf(M, sm[w]);
    float f[8];
    float Zb = 0.f;
#pragma unroll
    for (int w = 0; w < 8; w++) { f[w] = __expf(sm[w] - M); Zb += sz[w] * f[w]; }

    int idx = b * SPLITS + sp;
    if (threadIdx.x == 0) { g_pm[idx] = M; g_pz[idx] = Zb; }

    const float* sw = (const float*)sw4;
    for (int e = threadIdx.x; e < HH; e += 256) {
        float a = 0.f;
#pragma unroll
        for (int w = 0; w < 8; w++) a = fmaf(sw[w * HH + e], f[w], a);
        g_pw[(size_t)idx * HH + e] = a;
    }
}

// ---------------------------------------------------------------------------
// Kernel C: per-batch final combine. 64 blocks x 256 threads.
// Wv staged through smem in 32-row tiles (same pattern as prep).
// attn computed/written as float4.
// ---------------------------------------------------------------------------
__global__ void __launch_bounds__(256)
finalize_kernel(const float* __restrict__ Wv,
                const float* __restrict__ bv,
                float* __restrict__ out_ctx,
                float* __restrict__ out_attn) {
    int b = blockIdx.x, tid = threadIdx.x;
    __shared__ float wsh[HH];
    __shared__ float sW[32 * PP];   // 32KB tile

    float M = -INFINITY;
#pragma unroll
    for (int j = 0; j < SPLITS; j++) M = fmaxf(M, g_pm[b * SPLITS + j]);
    float f[SPLITS];
    float Z = 0.f;
#pragma unroll
    for (int j = 0; j < SPLITS; j++) {
        f[j] = __expf(g_pm[b * SPLITS + j] - M);
        Z += g_pz[b * SPLITS + j] * f[j];
    }
    float invZ = 1.f / Z;

    for (int e = tid; e < HH; e += 256) {
        float a = 0.f;
#pragma unroll
        for (int j = 0; j < SPLITS; j++)
            a = fmaf(g_pw[(size_t)(b * SPLITS + j) * HH + e], f[j], a);
        wsh[e] = a * invZ;
    }

    // context[b, tid] via smem-tiled Wv
    float acc = bv[tid];
    for (int t = 0; t < HH / 32; t++) {
        __syncthreads();
        const float4* src = (const float4*)(Wv + (size_t)t * 32 * PP);
        float4* dst = (float4*)sW;
#pragma unroll
        for (int i = 0; i < 8; i++) dst[tid + i * 256] = src[tid + i * 256];
        __syncthreads();
#pragma unroll
        for (int e = 0; e < 32; e++)
            acc = fmaf(wsh[t * 32 + e], sW[e * PP + tid], acc);
    }
    out_ctx[b * PP + tid] = acc;

    // attn (vectorized)
    const float4* sc4 = (const float4*)(g_scores + b * TT);
    float4* at4 = (float4*)(out_attn + b * TT);
    for (int i = tid; i < TT / 4; i += 256) {
        float4 v = sc4[i];
        v.x = __expf(v.x - M) * invZ;
        v.y = __expf(v.y - M) * invZ;
        v.z = __expf(v.z - M) * invZ;
        v.w = __expf(v.w - M) * invZ;
        at4[i] = v;
    }
}

// ---------------------------------------------------------------------------
// Launch. Input order (metadata): dec, enc, encoder_lens(unused), Wk, bk,
// Wv, bv, Wq, bq. Output: [context (B*P) | attn (B*T)] float32.
// ---------------------------------------------------------------------------
extern "C" void kernel_launch(void* const* d_in, const int* in_sizes, int n_in,
                              void* d_out, int out_size) {
    const float* dec = (const float*)d_in[0];
    const float* enc = (const float*)d_in[1];
    const float* Wk  = (const float*)d_in[3];
    const float* bk  = (const float*)d_in[4];
    const float* Wv  = (const float*)d_in[5];
    const float* bv  = (const float*)d_in[6];
    const float* Wq  = (const float*)d_in[7];
    const float* bq  = (const float*)d_in[8];
    float* out = (float*)d_out;

    prep_kernel<<<BB, 256>>>(dec, Wk, bk, Wq, bq);
    score_kernel<<<dim3(SPLITS, BB), 256>>>(enc);
    finalize_kernel<<<BB, 256>>>(Wv, bv, out, out + BB * PP);
}